// round 5
// baseline (speedup 1.0000x reference)
#include <cuda_runtime.h>
#include <math.h>

#define BB 4
#define CC 3
#define HH 384
#define WW 384
#define HWSZ (HH * WW)
#define CHW (CC * HWSZ)

#define INV2SC 50.0f            // 1/(2*0.1^2)
#define INV2SS (1.0f / 98.0f)   // 1/(2*7^2)
#define EPS_LP 1e-6f
#define LOG2E 1.4426950408889634f

__device__ __forceinline__ float exp2_f(float x) {
    float r;
    asm("ex2.approx.f32 %0, %1;" : "=f"(r) : "f"(x));
    return r;
}
__device__ __forceinline__ float lg2_f(float x) {
    float r;
    asm("lg2.approx.f32 %0, %1;" : "=f"(r) : "f"(x));
    return r;
}

// lp(d) = (d*d+eps)^0.4 = exp2(0.4*log2(d*d+eps))
__device__ __forceinline__ float lp_(float d) {
    return exp2_f(0.4f * lg2_f(fmaf(d, d, EPS_LP)));
}

// exp(-s/98) as compile-time literals (s = dy^2+dx^2, distinct values)
__device__ __forceinline__ constexpr float ws_of(int s) {
    return s == 1  ? 0.98984778f :
           s == 2  ? 0.97979867f :
           s == 4  ? 0.96000524f :
           s == 5  ? 0.95025928f :
           s == 8  ? 0.92161006f :
           s == 9  ? 0.91225415f :
           s == 10 ? 0.90299269f :
           s == 13 ? 0.87576888f :
                     0.83220750f;  // s == 18
}

// Half-set pair accumulation. CHECK=false: no bounds tests (interior blocks).
template<bool CHECK>
__device__ __forceinline__ float accum_pairs(
    const float* __restrict__ pi, const float* __restrict__ pt,
    float i0, float i1, float i2, float t0, float t1, float t2,
    int x, int y)
{
    float pacc = 0.0f;
#pragma unroll
    for (int dy = 0; dy <= 3; dy++) {
#pragma unroll
        for (int dx = -3; dx <= 3; dx++) {
            if (dy == 0 && dx <= 0) continue;     // compile-time skip
            if (CHECK) {
                if (!((y + dy) < HH && (unsigned)(x + dx) < (unsigned)WW))
                    continue;
            }
            const int q = dy * WW + dx;           // immediate offset
            const float iq0 = pi[q];
            const float iq1 = pi[q + HWSZ];
            const float iq2 = pi[q + 2 * HWSZ];
            const float tq0 = pt[q];
            const float tq1 = pt[q + HWSZ];
            const float tq2 = pt[q + 2 * HWSZ];

            const float d0 = i0 - iq0, d1 = i1 - iq1, d2 = i2 - iq2;
            const float e0 = t0 - tq0, e1 = t1 - tq1, e2 = t2 - tq2;
            const float a0 = fabsf(d0) - fabsf(e0);
            const float a1 = fabsf(d1) - fabsf(e1);
            const float a2 = fabsf(d2) - fabsf(e2);

            const float cd = fmaf(e0, e0, fmaf(e1, e1, e2 * e2));
            const int   s  = dy * dy + dx * dx;   // compile-time
            const float ws = ws_of(s);
            const float sc = -(float)s * INV2SS * LOG2E;       // literal
            const float wcs = exp2_f(fmaf(cd, -INV2SC * LOG2E, sc));

            const float sm = lp_(d0) + lp_(d1) + lp_(d2);
            const float ed = lp_(a0) + lp_(a1) + lp_(a2);

            pacc = fmaf(wcs, sm, pacc);
            pacc = fmaf(ws - wcs, ed, pacc);
        }
    }
    return pacc;
}

__global__ __launch_bounds__(256)
void pair_kernel(const float* __restrict__ inp,
                 const float* __restrict__ tgt,
                 float* __restrict__ out) {
    const int x = blockIdx.x * 32 + threadIdx.x;
    const int y = blockIdx.y * 8 + threadIdx.y;
    const int b = blockIdx.z;
    const int pidx = y * WW + x;

    const float* pi = inp + b * CHW + pidx;
    const float* pt = tgt + b * CHW + pidx;

    const float i0 = pi[0], i1 = pi[HWSZ], i2 = pi[2 * HWSZ];
    const float t0 = pt[0], t1 = pt[HWSZ], t2 = pt[2 * HWSZ];

    // block-uniform: can this block touch any image border (3-px band)?
    const bool interior = (blockIdx.x > 0) & (blockIdx.x + 1 < gridDim.x) &
                          (blockIdx.y > 0) & (blockIdx.y + 1 < gridDim.y);

    float pacc;
    float bacc = 0.0f;

    if (interior) {
        pacc = accum_pairs<false>(pi, pt, i0, i1, i2, t0, t1, t2, x, y);
    } else {
        pacc = accum_pairs<true>(pi, pt, i0, i1, i2, t0, t1, t2, x, y);

        // unpaired clamped terms (weight 1) for edge-band pixels only
        if (x < 3 || x >= WW - 3 || y < 3 || y >= HH - 3) {
#pragma unroll 1
            for (int dy = -3; dy <= 3; dy++) {
#pragma unroll 1
                for (int dx = -3; dx <= 3; dx++) {
                    int qx = x + dx, qy = y + dy;
                    const bool oob = ((unsigned)qx >= (unsigned)WW) ||
                                     ((unsigned)qy >= (unsigned)HH);
                    if (!oob) continue;            // includes (0,0)
                    qx = qx < 0 ? 0 : (qx >= WW ? WW - 1 : qx);
                    qy = qy < 0 ? 0 : (qy >= HH ? HH - 1 : qy);
                    const int q = (qy - y) * WW + (qx - x);

                    const float iq0 = pi[q];
                    const float iq1 = pi[q + HWSZ];
                    const float iq2 = pi[q + 2 * HWSZ];
                    const float tq0 = pt[q];
                    const float tq1 = pt[q + HWSZ];
                    const float tq2 = pt[q + 2 * HWSZ];

                    const float d0 = i0 - iq0, d1 = i1 - iq1, d2 = i2 - iq2;
                    const float e0 = t0 - tq0, e1 = t1 - tq1, e2 = t2 - tq2;

                    const float cd = fmaf(e0, e0, fmaf(e1, e1, e2 * e2));
                    const float sdist = (float)(dy * dy + dx * dx);
                    const float ws = __expf(-sdist * INV2SS);
                    const float wcs = __expf(-fmaf(cd, INV2SC, sdist * INV2SS));

                    const float sm = lp_(d0) + lp_(d1) + lp_(d2);
                    const float ed = lp_(fabsf(d0) - fabsf(e0))
                                   + lp_(fabsf(d1) - fabsf(e1))
                                   + lp_(fabsf(d2) - fabsf(e2));

                    bacc = fmaf(wcs, sm, bacc);
                    bacc = fmaf(ws - wcs, ed, bacc);
                }
            }
        }
    }

    const float l2 = (i0 - t0) * (i0 - t0)
                   + (i1 - t1) * (i1 - t1)
                   + (i2 - t2) * (i2 - t2);
    float acc = fmaf(2.0f, pacc, l2 + bacc);

    // ---- reduction: warp shuffle -> block -> one atomic ----
    const unsigned FULL = 0xFFFFFFFFu;
#pragma unroll
    for (int off = 16; off > 0; off >>= 1)
        acc += __shfl_down_sync(FULL, acc, off);

    __shared__ float wsum[8];
    const int tid = threadIdx.y * 32 + threadIdx.x;
    const int wid = tid >> 5, lid = tid & 31;
    if (lid == 0) wsum[wid] = acc;
    __syncthreads();
    if (wid == 0) {
        float v = (lid < 8) ? wsum[lid] : 0.0f;
#pragma unroll
        for (int off = 4; off > 0; off >>= 1)
            v += __shfl_down_sync(FULL, v, off);
        if (lid == 0) {
            const float inv_n = 1.0f / (float)(BB * CC * HH * WW);
            atomicAdd(out, v * inv_n);
        }
    }
}

extern "C" void kernel_launch(void* const* d_in, const int* in_sizes, int n_in,
                              void* d_out, int out_size) {
    (void)in_sizes; (void)n_in;
    const float* inp = (const float*)d_in[0];
    const float* tgt = (const float*)d_in[1];
    float* out = (float*)d_out;

    if (out_size >= 1) cudaMemsetAsync(out, 0, sizeof(float));

    dim3 block(32, 8, 1);
    dim3 grid(WW / 32, HH / 8, BB);
    pair_kernel<<<grid, block>>>(inp, tgt, out);
}

// round 6
// speedup vs baseline: 1.0346x; 1.0346x over previous
#include <cuda_runtime.h>
#include <math.h>

#define BB 4
#define CC 3
#define HH 384
#define WW 384
#define HWSZ (HH * WW)
#define CHW (CC * HWSZ)

#define INV2SC 50.0f            // 1/(2*0.1^2)
#define INV2SS (1.0f / 98.0f)   // 1/(2*7^2)
#define EPS_LP 1e-6f
#define LOG2E 1.4426950408889634f

__device__ __forceinline__ float exp2_f(float x) {
    float r;
    asm("ex2.approx.f32 %0, %1;" : "=f"(r) : "f"(x));
    return r;
}
__device__ __forceinline__ float lg2_f(float x) {
    float r;
    asm("lg2.approx.f32 %0, %1;" : "=f"(r) : "f"(x));
    return r;
}

// lp(d) = (d*d+eps)^0.4 = exp2(0.4*log2(d*d+eps))
__device__ __forceinline__ float lp_(float d) {
    return exp2_f(0.4f * lg2_f(fmaf(d, d, EPS_LP)));
}

// exp(-s/98) as compile-time literals (s = dy^2+dx^2 over the half-set)
__device__ __forceinline__ constexpr float ws_of(int s) {
    return s == 1  ? 0.98984778f :
           s == 2  ? 0.97979867f :
           s == 4  ? 0.96000524f :
           s == 5  ? 0.95025928f :
           s == 8  ? 0.92161006f :
           s == 9  ? 0.91225415f :
           s == 10 ? 0.90299269f :
           s == 13 ? 0.87576888f :
                     0.83220750f;  // s == 18
}

__global__ __launch_bounds__(256)
void pair_kernel(const float* __restrict__ inp,
                 const float* __restrict__ tgt,
                 float* __restrict__ out) {
    const int x = blockIdx.x * 32 + threadIdx.x;
    const int y = blockIdx.y * 8 + threadIdx.y;
    const int b = blockIdx.z;
    const int pidx = y * WW + x;

    const float* pi = inp + b * CHW + pidx;
    const float* pt = tgt + b * CHW + pidx;

    const float i0 = pi[0], i1 = pi[HWSZ], i2 = pi[2 * HWSZ];
    const float t0 = pt[0], t1 = pt[HWSZ], t2 = pt[2 * HWSZ];

    float pacc = 0.0f;

    // Single checked half-set body (24 offsets), each term counted twice.
    // Column predicates x+dx<W are loop-invariant across dy; ptxas CSEs them.
#pragma unroll
    for (int dy = 0; dy <= 3; dy++) {
        const bool vy = (y + dy) < HH;       // dy==0 row: always true
#pragma unroll
        for (int dx = -3; dx <= 3; dx++) {
            if (dy == 0 && dx <= 0) continue;    // compile-time skip
            if (vy && ((unsigned)(x + dx) < (unsigned)WW)) {
                const int q = dy * WW + dx;      // immediate offset
                const float iq0 = pi[q];
                const float iq1 = pi[q + HWSZ];
                const float iq2 = pi[q + 2 * HWSZ];
                const float tq0 = pt[q];
                const float tq1 = pt[q + HWSZ];
                const float tq2 = pt[q + 2 * HWSZ];

                const float d0 = i0 - iq0, d1 = i1 - iq1, d2 = i2 - iq2;
                const float e0 = t0 - tq0, e1 = t1 - tq1, e2 = t2 - tq2;
                const float a0 = fabsf(d0) - fabsf(e0);
                const float a1 = fabsf(d1) - fabsf(e1);
                const float a2 = fabsf(d2) - fabsf(e2);

                const float cd = fmaf(e0, e0, fmaf(e1, e1, e2 * e2));
                const int   s  = dy * dy + dx * dx;           // compile-time
                const float ws = ws_of(s);
                const float sc = -(float)s * INV2SS * LOG2E;  // literal
                const float wcs = exp2_f(fmaf(cd, -INV2SC * LOG2E, sc));

                const float sm = lp_(d0) + lp_(d1) + lp_(d2);
                const float ed = lp_(a0) + lp_(a1) + lp_(a2);

                pacc = fmaf(wcs, sm, pacc);
                pacc = fmaf(ws - wcs, ed, pacc);
            }
        }
    }

    // Unpaired clamped terms (weight 1): compact rolled loop, edge band only.
    float bacc = 0.0f;
    if (x < 3 || x >= WW - 3 || y < 3 || y >= HH - 3) {
#pragma unroll 1
        for (int dy = -3; dy <= 3; dy++) {
#pragma unroll 1
            for (int dx = -3; dx <= 3; dx++) {
                int qx = x + dx, qy = y + dy;
                const bool oob = ((unsigned)qx >= (unsigned)WW) ||
                                 ((unsigned)qy >= (unsigned)HH);
                if (!oob) continue;               // includes (0,0)
                qx = qx < 0 ? 0 : (qx >= WW ? WW - 1 : qx);
                qy = qy < 0 ? 0 : (qy >= HH ? HH - 1 : qy);
                const int q = (qy - y) * WW + (qx - x);

                const float iq0 = pi[q];
                const float iq1 = pi[q + HWSZ];
                const float iq2 = pi[q + 2 * HWSZ];
                const float tq0 = pt[q];
                const float tq1 = pt[q + HWSZ];
                const float tq2 = pt[q + 2 * HWSZ];

                const float d0 = i0 - iq0, d1 = i1 - iq1, d2 = i2 - iq2;
                const float e0 = t0 - tq0, e1 = t1 - tq1, e2 = t2 - tq2;

                const float cd = fmaf(e0, e0, fmaf(e1, e1, e2 * e2));
                const float sdist = (float)(dy * dy + dx * dx);
                const float ws = __expf(-sdist * INV2SS);
                const float wcs = __expf(-fmaf(cd, INV2SC, sdist * INV2SS));

                const float sm = lp_(d0) + lp_(d1) + lp_(d2);
                const float ed = lp_(fabsf(d0) - fabsf(e0))
                               + lp_(fabsf(d1) - fabsf(e1))
                               + lp_(fabsf(d2) - fabsf(e2));

                bacc = fmaf(wcs, sm, bacc);
                bacc = fmaf(ws - wcs, ed, bacc);
            }
        }
    }

    const float l2 = (i0 - t0) * (i0 - t0)
                   + (i1 - t1) * (i1 - t1)
                   + (i2 - t2) * (i2 - t2);
    float acc = fmaf(2.0f, pacc, l2 + bacc);

    // ---- reduction: warp shuffle -> block -> one atomic ----
    const unsigned FULL = 0xFFFFFFFFu;
#pragma unroll
    for (int off = 16; off > 0; off >>= 1)
        acc += __shfl_down_sync(FULL, acc, off);

    __shared__ float wsum[8];
    const int tid = threadIdx.y * 32 + threadIdx.x;
    const int wid = tid >> 5, lid = tid & 31;
    if (lid == 0) wsum[wid] = acc;
    __syncthreads();
    if (wid == 0) {
        float v = (lid < 8) ? wsum[lid] : 0.0f;
#pragma unroll
        for (int off = 4; off > 0; off >>= 1)
            v += __shfl_down_sync(FULL, v, off);
        if (lid == 0) {
            const float inv_n = 1.0f / (float)(BB * CC * HH * WW);
            atomicAdd(out, v * inv_n);
        }
    }
}

extern "C" void kernel_launch(void* const* d_in, const int* in_sizes, int n_in,
                              void* d_out, int out_size) {
    (void)in_sizes; (void)n_in;
    const float* inp = (const float*)d_in[0];
    const float* tgt = (const float*)d_in[1];
    float* out = (float*)d_out;

    if (out_size >= 1) cudaMemsetAsync(out, 0, sizeof(float));

    dim3 block(32, 8, 1);
    dim3 grid(WW / 32, HH / 8, BB);
    pair_kernel<<<grid, block>>>(inp, tgt, out);
}

// round 7
// speedup vs baseline: 1.1024x; 1.0656x over previous
#include <cuda_runtime.h>
#include <math.h>

#define BB 4
#define CC 3
#define HH 384
#define WW 384
#define HWSZ (HH * WW)
#define CHW (CC * HWSZ)

#define INV2SC 50.0f            // 1/(2*0.1^2)
#define INV2SS (1.0f / 98.0f)   // 1/(2*7^2)
#define EPS_LP 1e-6f

// Border pixels per image: 2 strips of 3x384 + 378 rows x 6 cols
#define NBORDER (2 * 3 * WW + (HH - 6) * 6)   // 4572
#define NBTOT (NBORDER * BB)                  // 18288

// lp(d) = (d*d + eps)^(p/2) with p=0.8 -> (d*d+eps)^0.4
__device__ __forceinline__ float lp_term(float d) {
    return __powf(fmaf(d, d, EPS_LP), 0.4f);
}

// warp -> block reduction, one atomic per block (pre-scaled by 1/n)
__device__ __forceinline__ void reduce_add(float acc, float* out, int tid) {
    const unsigned FULL = 0xFFFFFFFFu;
#pragma unroll
    for (int off = 16; off > 0; off >>= 1)
        acc += __shfl_down_sync(FULL, acc, off);
    __shared__ float wsum[8];
    const int wid = tid >> 5, lid = tid & 31;
    if (lid == 0) wsum[wid] = acc;
    __syncthreads();
    if (wid == 0) {
        float v = (lid < 8) ? wsum[lid] : 0.0f;
#pragma unroll
        for (int off = 4; off > 0; off >>= 1)
            v += __shfl_down_sync(FULL, v, off);
        if (lid == 0) {
            const float inv_n = 1.0f / (float)(BB * CC * HH * WW);
            atomicAdd(out, v * inv_n);
        }
    }
}

// Main kernel: all pixels, 24-offset half-set (dy>0, or dy==0 && dx>0),
// in-bounds neighbors only; each term counted twice (exact pair symmetry).
// NO border handling here — keeping this kernel clean is worth ~7us (R4-R6 data).
__global__ __launch_bounds__(256)
void pair_kernel(const float* __restrict__ inp,
                 const float* __restrict__ tgt,
                 float* __restrict__ out) {
    const int x = blockIdx.x * 32 + threadIdx.x;
    const int y = blockIdx.y * 8 + threadIdx.y;
    const int b = blockIdx.z;
    const int pidx = y * WW + x;

    const float* pi = inp + b * CHW + pidx;
    const float* pt = tgt + b * CHW + pidx;

    const float i0 = pi[0], i1 = pi[HWSZ], i2 = pi[2 * HWSZ];
    const float t0 = pt[0], t1 = pt[HWSZ], t2 = pt[2 * HWSZ];

    // spatial weight components exp(-k^2/98); 3 MUFU per thread, negligible
    float wky[4];
    wky[0] = 1.0f;
    wky[1] = __expf(-1.0f * INV2SS);
    wky[2] = __expf(-4.0f * INV2SS);
    wky[3] = __expf(-9.0f * INV2SS);

    float pacc = 0.0f;

#pragma unroll
    for (int dy = 0; dy <= 3; dy++) {
        const bool vy = (y + dy) < HH;
#pragma unroll
        for (int dx = -3; dx <= 3; dx++) {
            if (dy == 0 && dx <= 0) continue;      // compile-time
            const bool v = vy && ((unsigned)(x + dx) < (unsigned)WW);
            if (v) {
                const int q = dy * WW + dx;        // compile-time immediate
                const float iq0 = __ldg(pi + q);
                const float iq1 = __ldg(pi + q + HWSZ);
                const float iq2 = __ldg(pi + q + 2 * HWSZ);
                const float tq0 = __ldg(pt + q);
                const float tq1 = __ldg(pt + q + HWSZ);
                const float tq2 = __ldg(pt + q + 2 * HWSZ);

                const float d0 = i0 - iq0, d1 = i1 - iq1, d2 = i2 - iq2;
                const float e0 = t0 - tq0, e1 = t1 - tq1, e2 = t2 - tq2;

                const float cd = fmaf(e0, e0, fmaf(e1, e1, e2 * e2));
                const int adx = dx < 0 ? -dx : dx;
                const float ws = wky[dy] * wky[adx];
                const float sconst = (float)(dy * dy + dx * dx) * INV2SS;
                const float wcs = __expf(-fmaf(cd, INV2SC, sconst)); // ws*wc fused

                const float sm = lp_term(d0) + lp_term(d1) + lp_term(d2);
                const float ed = lp_term(fabsf(d0) - fabsf(e0))
                               + lp_term(fabsf(d1) - fabsf(e1))
                               + lp_term(fabsf(d2) - fabsf(e2));

                pacc = fmaf(wcs, sm, pacc);
                pacc = fmaf(ws - wcs, ed, pacc);
            }
        }
    }

    const float l2 = (i0 - t0) * (i0 - t0)
                   + (i1 - t1) * (i1 - t1)
                   + (i2 - t2) * (i2 - t2);
    const float acc = fmaf(2.0f, pacc, l2);

    reduce_add(acc, out, threadIdx.y * 32 + threadIdx.x);
}

// Border kernel: only the clamped (out-of-bounds) ordered terms, weight 1.
__global__ __launch_bounds__(256)
void border_kernel(const float* __restrict__ inp,
                   const float* __restrict__ tgt,
                   float* __restrict__ out) {
    const int gid = blockIdx.x * 256 + threadIdx.x;
    float acc = 0.0f;

    if (gid < NBTOT) {
        const int b = gid / NBORDER;
        const int r = gid % NBORDER;
        int x, y;
        if (r < 3 * WW) {                    // top rows 0..2
            y = r / WW; x = r % WW;
        } else if (r < 6 * WW) {             // bottom rows 381..383
            const int r2 = r - 3 * WW;
            y = (HH - 3) + r2 / WW; x = r2 % WW;
        } else {                             // side cols, rows 3..380
            const int r3 = r - 6 * WW;
            y = 3 + r3 / 6;
            const int c = r3 % 6;
            x = (c < 3) ? c : (WW - 6 + c);  // 0,1,2 or 381,382,383
        }
        const int pidx = y * WW + x;
        const float* pi = inp + b * CHW + pidx;
        const float* pt = tgt + b * CHW + pidx;

        const float i0 = pi[0], i1 = pi[HWSZ], i2 = pi[2 * HWSZ];
        const float t0 = pt[0], t1 = pt[HWSZ], t2 = pt[2 * HWSZ];

        float wky[4];
        wky[0] = 1.0f;
        wky[1] = __expf(-1.0f * INV2SS);
        wky[2] = __expf(-4.0f * INV2SS);
        wky[3] = __expf(-9.0f * INV2SS);

#pragma unroll 1
        for (int dy = -3; dy <= 3; dy++) {
#pragma unroll 1
            for (int dx = -3; dx <= 3; dx++) {
                if (dy == 0 && dx == 0) continue;
                int qx = x + dx, qy = y + dy;
                const bool oob = ((unsigned)qx >= (unsigned)WW) ||
                                 ((unsigned)qy >= (unsigned)HH);
                if (oob) {
                    qx = qx < 0 ? 0 : (qx >= WW ? WW - 1 : qx);
                    qy = qy < 0 ? 0 : (qy >= HH ? HH - 1 : qy);
                    const int q = (qy - y) * WW + (qx - x);  // rel to pidx

                    const float iq0 = __ldg(pi + q);
                    const float iq1 = __ldg(pi + q + HWSZ);
                    const float iq2 = __ldg(pi + q + 2 * HWSZ);
                    const float tq0 = __ldg(pt + q);
                    const float tq1 = __ldg(pt + q + HWSZ);
                    const float tq2 = __ldg(pt + q + 2 * HWSZ);

                    const float d0 = i0 - iq0, d1 = i1 - iq1, d2 = i2 - iq2;
                    const float e0 = t0 - tq0, e1 = t1 - tq1, e2 = t2 - tq2;

                    const float cd = fmaf(e0, e0, fmaf(e1, e1, e2 * e2));
                    const int ady = dy < 0 ? -dy : dy;
                    const int adx = dx < 0 ? -dx : dx;
                    const float ws = wky[ady] * wky[adx];
                    const float sconst = (float)(dy * dy + dx * dx) * INV2SS;
                    const float wcs = __expf(-fmaf(cd, INV2SC, sconst));

                    const float sm = lp_term(d0) + lp_term(d1) + lp_term(d2);
                    const float ed = lp_term(fabsf(d0) - fabsf(e0))
                                   + lp_term(fabsf(d1) - fabsf(e1))
                                   + lp_term(fabsf(d2) - fabsf(e2));

                    acc = fmaf(wcs, sm, acc);
                    acc = fmaf(ws - wcs, ed, acc);
                }
            }
        }
    }

    reduce_add(acc, out, threadIdx.x);
}

extern "C" void kernel_launch(void* const* d_in, const int* in_sizes, int n_in,
                              void* d_out, int out_size) {
    (void)in_sizes; (void)n_in;
    const float* inp = (const float*)d_in[0];
    const float* tgt = (const float*)d_in[1];
    float* out = (float*)d_out;

    if (out_size >= 1) cudaMemsetAsync(out, 0, sizeof(float));

    border_kernel<<<(NBTOT + 255) / 256, 256>>>(inp, tgt, out);

    dim3 block(32, 8, 1);
    dim3 grid(WW / 32, HH / 8, BB);
    pair_kernel<<<grid, block>>>(inp, tgt, out);
}